// round 2
// baseline (speedup 1.0000x reference)
#include <cuda_runtime.h>
#include <math.h>

#define BB 8
#define LL 2048
#define KSEL 64
#define ROWS 16
#define NBINS 256
#define MAXC 256
#define THREADS 256

// scratch (no cudaMalloc allowed)
__device__ float g_rho[BB * LL];
__device__ float g_rowsum[BB * LL];
__device__ int   g_seq64;

// ---------------- seq dtype detection (int64 vs int32) ----------------
// Values are in [0,20). If stored as int64 (little-endian), odd 32-bit words
// are all zero. Probability of that for int32 data is (1/20)^64 ~ 0.
__global__ void detect_kernel(const int* __restrict__ seqw) {
    if (threadIdx.x == 0 && blockIdx.x == 0) {
        int is64 = 1;
        for (int k = 0; k < 64; k++)
            if (seqw[2 * k + 1] != 0) { is64 = 0; break; }
        g_seq64 = is64;
    }
}

// ---------------- per-residue learned radius ----------------
__global__ void rho_kernel(const void* __restrict__ seq,
                           const float* __restrict__ emb,
                           const float* __restrict__ w,
                           const float* __restrict__ bparam) {
    int idx = blockIdx.x * blockDim.x + threadIdx.x;
    if (idx >= BB * LL) return;
    int s;
    if (g_seq64) s = (int)((const long long*)seq)[idx];
    else         s = ((const int*)seq)[idx];
    const float* e = emb + s * 16;
    float x = bparam[0];
#pragma unroll
    for (int d = 0; d < 16; d++) x = fmaf(e[d], w[d], x);
    float sig = 1.0f / (1.0f + expf(-x));
    g_rho[idx] = 1.6f + 1.2f * sig;   // RHO_MIN + (RHO_MAX-RHO_MIN)*sigmoid
}

// ---------------- contribution for a selected pair ----------------
__device__ __forceinline__ float contrib(float d2, float r0) {
    float r = sqrtf(fmaxf(d2, 1e-12f));
    float x = (r0 - r) * (1.0f / 0.3f);            // (r0-r)/(DELTA+1e-12)
    // numerically stable softplus: max(x,0) + log1p(exp(-|x|))
    float sp = fmaxf(x, 0.0f) + log1pf(expf(-fabsf(x)));
    float t = fminf(fmaxf((r - 8.0f) * 0.5f, 0.0f), 1.0f);  // (r-R_ON)/(R_CUT-R_ON)
    float sw = 1.0f - t * t * (3.0f - 2.0f * t);
    return 10.0f * sp * sw;                         // WALL * softplus * switch
}

// ---------------- main: per-row exact top-K via histogram select ----------------
__global__ void __launch_bounds__(THREADS)
main_kernel(const float* __restrict__ R) {
    __shared__ float4 pts[LL];       // x,y,z,rho
    __shared__ float  d2s[LL];
    __shared__ int    hist[NBINS];
    __shared__ float  cand_d2[MAXC];
    __shared__ int    cand_j[MAXC];
    __shared__ float  red[THREADS];
    __shared__ int    sh_t, sh_m, sh_cnt;

    const int rows_per_batch = LL / ROWS;
    int b    = blockIdx.x / rows_per_batch;
    int row0 = (blockIdx.x % rows_per_batch) * ROWS;
    int tid  = threadIdx.x;

    const float* Rb = R + (size_t)b * LL * 3;
    for (int j = tid; j < LL; j += THREADS) {
        float x = Rb[j * 3 + 0];
        float y = Rb[j * 3 + 1];
        float z = Rb[j * 3 + 2];
        pts[j] = make_float4(x, y, z, g_rho[b * LL + j]);
    }
    __syncthreads();

    for (int r = 0; r < ROWS; r++) {
        int i = row0 + r;
        float4 pi = pts[i];

        hist[tid] = 0;                 // THREADS == NBINS
        if (tid == 0) sh_cnt = 0;
        __syncthreads();

        // ---- pass 1: squared distances + histogram over d2 in [0,100) ----
        for (int j = tid; j < LL; j += THREADS) {
            float4 pj = pts[j];
            float dx = pi.x - pj.x, dy = pi.y - pj.y, dz = pi.z - pj.z;
            float d2 = fmaf(dx, dx, fmaf(dy, dy, dz * dz));
            int dj = j - i; if (dj < 0) dj = -dj;
            if (dj <= 2) d2 = 1e12f;   // excluded pairs
            d2s[j] = d2;
            if (d2 < 100.0f) {
                int bin = (int)(d2 * 2.56f);
                if (bin > 255) bin = 255;
                atomicAdd(&hist[bin], 1);
            }
        }
        __syncthreads();

        // ---- warp-0 scan: find threshold bin t and boundary need m ----
        if (tid < 32) {
            int lane = tid;
            int loc[8]; int s = 0;
#pragma unroll
            for (int k = 0; k < 8; k++) { loc[k] = hist[lane * 8 + k]; s += loc[k]; }
            int scan = s;
#pragma unroll
            for (int off = 1; off < 32; off <<= 1) {
                int v = __shfl_up_sync(0xffffffffu, scan, off);
                if (lane >= off) scan += v;
            }
            int total  = __shfl_sync(0xffffffffu, scan, 31);
            int before = scan - s;
            if (lane == 0 && total <= KSEL) { sh_t = NBINS; sh_m = 0; }
            if (total > KSEL && before < KSEL && scan >= KSEL) {
                int cum = before;
#pragma unroll
                for (int k = 0; k < 8; k++) {
                    if (cum + loc[k] >= KSEL) { sh_t = lane * 8 + k; sh_m = KSEL - cum; break; }
                    cum += loc[k];
                }
            }
        }
        __syncthreads();
        int tbin = sh_t, m = sh_m;

        // ---- pass 2: accumulate bins < t; collect boundary candidates ----
        float lsum = 0.0f;
        for (int j = tid; j < LL; j += THREADS) {
            float d2 = d2s[j];
            if (d2 < 100.0f) {
                int bin = (int)(d2 * 2.56f);
                if (bin > 255) bin = 255;
                if (bin < tbin) {
                    lsum += contrib(d2, pi.w + pts[j].w);
                } else if (bin == tbin) {
                    int pos = atomicAdd(&sh_cnt, 1);
                    if (pos < MAXC) { cand_d2[pos] = d2; cand_j[pos] = j; }
                }
            }
        }
        __syncthreads();

        // ---- exact rank-select inside boundary bin (stable: index tiebreak) ----
        int c = sh_cnt; if (c > MAXC) c = MAXC;
        for (int k = tid; k < c; k += THREADS) {
            float dk = cand_d2[k]; int jk = cand_j[k];
            int rank = 0;
            for (int l = 0; l < c; l++) {
                float dl = cand_d2[l];
                rank += (dl < dk) || (dl == dk && cand_j[l] < jk);
            }
            if (rank < m) lsum += contrib(dk, pi.w + pts[jk].w);
        }

        // ---- deterministic tree reduction ----
        red[tid] = lsum;
        __syncthreads();
        for (int s2 = THREADS / 2; s2 > 0; s2 >>= 1) {
            if (tid < s2) red[tid] += red[tid + s2];
            __syncthreads();
        }
        if (tid == 0) g_rowsum[b * LL + i] = red[0];
        __syncthreads();
    }
}

// ---------------- per-batch deterministic reduction ----------------
__global__ void reduce_kernel(float* __restrict__ out) {
    __shared__ float red[256];
    int b = blockIdx.x;
    float s = 0.0f;
    for (int i = threadIdx.x; i < LL; i += 256) s += g_rowsum[b * LL + i];
    red[threadIdx.x] = s;
    __syncthreads();
    for (int k = 128; k > 0; k >>= 1) {
        if (threadIdx.x < k) red[threadIdx.x] += red[threadIdx.x + k];
        __syncthreads();
    }
    if (threadIdx.x == 0) out[b] = red[0];
}

extern "C" void kernel_launch(void* const* d_in, const int* in_sizes, int n_in,
                              void* d_out, int out_size) {
    const float* R   = (const float*)d_in[0];
    const void*  seq = d_in[1];
    const float* emb = (const float*)d_in[2];
    const float* w   = (const float*)d_in[3];
    const float* bp  = (const float*)d_in[4];
    float* out = (float*)d_out;

    detect_kernel<<<1, 32>>>((const int*)seq);
    rho_kernel<<<(BB * LL + 255) / 256, 256>>>(seq, emb, w, bp);
    main_kernel<<<(BB * LL) / ROWS, THREADS>>>(R);
    reduce_kernel<<<BB, 256>>>(out);
}